// round 2
// baseline (speedup 1.0000x reference)
#include <cuda_runtime.h>
#include <cuda_bf16.h>
#include <math.h>
#include <stdint.h>

#define BB 2
#define NNODES 4096
#define DIMF 128
#define MDIM 16
#define KNN 32
#define HID 530
#define NODES (BB*NNODES)          // 8192
#define NODE_OUT_ELEMS (NODES*DIMF)

// ---------------- scratch (static device arrays; no allocation) -------------
__device__ float g_A[NODES * HID];     // feats@We1[0:128]+be1
__device__ float g_B[NODES * HID];     // feats@We1[128:256]
__device__ float g_XC[NODES * 144];    // [feats | m_i]
__device__ float g_H1[NODES * 256];    // node hidden
__device__ int   g_knn[NODES * KNN];

__device__ __forceinline__ float silu_f(float x) {
    float e = __expf(-x);
    return __fdividef(x, 1.0f + e);
}

__device__ __forceinline__ float dist2_f(float dx, float dy, float dz) {
    // match reference (no FMA contraction, left-assoc sum)
    return __fadd_rn(__fadd_rn(__fmul_rn(dx, dx), __fmul_rn(dy, dy)), __fmul_rn(dz, dz));
}

// ---------------------------------------------------------------------------
// KNN: one warp per (b,i). Unsorted top-32 set via warp REDUX threshold.
// ---------------------------------------------------------------------------
__global__ __launch_bounds__(256) void knn_kernel(const float* __restrict__ coors) {
    const unsigned FULL = 0xffffffffu;
    int w    = blockIdx.x * 8 + (threadIdx.x >> 5);
    int lane = threadIdx.x & 31;
    int b = w >> 12;
    int i = w & (NNODES - 1);
    const float* cb = coors + (size_t)b * NNODES * 3;
    float qx = cb[3 * i + 0], qy = cb[3 * i + 1], qz = cb[3 * i + 2];

    // seed with candidates j = 0..31
    float dx = qx - cb[3 * lane + 0];
    float dy = qy - cb[3 * lane + 1];
    float dz = qz - cb[3 * lane + 2];
    unsigned bu = __float_as_uint(dist2_f(dx, dy, dz)); // nonneg: bit order == value order
    int bj = lane;
    unsigned curmax = __reduce_max_sync(FULL, bu);

    for (int j0 = 32; j0 < NNODES; j0 += 32) {
        int j = j0 + lane;
        float ex = qx - cb[3 * j + 0];
        float ey = qy - cb[3 * j + 1];
        float ez = qz - cb[3 * j + 2];
        unsigned du = __float_as_uint(dist2_f(ex, ey, ez));
        unsigned mask = __ballot_sync(FULL, du < curmax);
        while (mask) {
            int src = __ffs(mask) - 1;
            mask &= mask - 1;
            unsigned dc = __shfl_sync(FULL, du, src);
            if (dc < curmax) {  // uniform
                unsigned mm = __ballot_sync(FULL, bu == curmax);
                int ml = __ffs(mm) - 1;
                if (lane == ml) { bu = dc; bj = j0 + src; }
                curmax = __reduce_max_sync(FULL, bu);
            }
        }
    }
    g_knn[(size_t)w * KNN + lane] = bj;
}

// ---------------------------------------------------------------------------
// Generic tiled fp32 GEMM: C[8192 x N] = act(X[8192 x K] @ W[K x N] + bias) (+resid)
// BM=BN=64, BK=16, 256 threads, 4x4 micro-tile. K multiple of 16, ldx mult of 4.
// ---------------------------------------------------------------------------
__global__ __launch_bounds__(256) void gemm_kernel(
    const float* __restrict__ X, int ldx,
    const float* __restrict__ W, int ldw,
    const float* __restrict__ bias,
    const float* __restrict__ resid,
    float* __restrict__ C, int ldc,
    int N, int K, int act)
{
    __shared__ float Xs[16][68];
    __shared__ float Ws[16][68];
    int tid = threadIdx.x;
    int tx = tid & 15, ty = tid >> 4;
    int m0 = blockIdx.y * 64, n0 = blockIdx.x * 64;

    int lm  = tid >> 2;
    int lk  = (tid & 3) * 4;
    int wn  = tid & 63;
    int wkb = (tid >> 6) * 4;

    float acc[4][4];
#pragma unroll
    for (int a = 0; a < 4; a++)
#pragma unroll
        for (int c = 0; c < 4; c++) acc[a][c] = 0.f;

    for (int kt = 0; kt < K; kt += 16) {
        float4 xv = *reinterpret_cast<const float4*>(X + (size_t)(m0 + lm) * ldx + kt + lk);
        Xs[lk + 0][lm] = xv.x;
        Xs[lk + 1][lm] = xv.y;
        Xs[lk + 2][lm] = xv.z;
        Xs[lk + 3][lm] = xv.w;
#pragma unroll
        for (int q = 0; q < 4; q++) {
            int k = wkb + q;
            float v = (n0 + wn < N) ? W[(size_t)(kt + k) * ldw + n0 + wn] : 0.f;
            Ws[k][wn] = v;
        }
        __syncthreads();
#pragma unroll
        for (int k = 0; k < 16; k++) {
            float4 a4 = *reinterpret_cast<const float4*>(&Xs[k][ty * 4]);
            float4 b4 = *reinterpret_cast<const float4*>(&Ws[k][tx * 4]);
            float av[4] = {a4.x, a4.y, a4.z, a4.w};
            float bv[4] = {b4.x, b4.y, b4.z, b4.w};
#pragma unroll
            for (int mi = 0; mi < 4; mi++)
#pragma unroll
                for (int ni = 0; ni < 4; ni++)
                    acc[mi][ni] = fmaf(av[mi], bv[ni], acc[mi][ni]);
        }
        __syncthreads();
    }

#pragma unroll
    for (int mi = 0; mi < 4; mi++) {
        int m = m0 + ty * 4 + mi;
#pragma unroll
        for (int ni = 0; ni < 4; ni++) {
            int n = n0 + tx * 4 + ni;
            if (n < N) {
                float v = acc[mi][ni];
                if (bias) v += bias[n];
                if (act) v = silu_f(v);
                if (resid) v += resid[(size_t)m * ldc + n];
                C[(size_t)m * ldc + n] = v;
            }
        }
    }
}

// ---------------------------------------------------------------------------
// copy feats into XC[:, 0:128]
// ---------------------------------------------------------------------------
__global__ __launch_bounds__(256) void copy_feats_kernel(const float* __restrict__ feats) {
    int idx = blockIdx.x * 256 + threadIdx.x;  // over NODES*128
    int n = idx >> 7, c = idx & 127;
    g_XC[(size_t)n * 144 + c] = feats[idx];
}

// ---------------------------------------------------------------------------
// Edge kernel: 256 threads, 4 nodes per block. Warp w handles edges 4w..4w+3
// of the current node, lanes stride the 530 channels. Fused second-layer GEMM
// accumulation in registers, warp-reduce, then coors MLP + m_i in shared.
// ---------------------------------------------------------------------------
#define EK_SMEM_FLOATS (10600 + 6360 + 1024 + 64 + 64 + 16 + 384 + 128 + 512 + 32 + 32)

__global__ __launch_bounds__(256, 2) void edge_kernel(
    const float* __restrict__ coors,
    const float* __restrict__ We1,
    const float* __restrict__ We2,
    const float* __restrict__ be2,
    const float* __restrict__ Wc1,
    const float* __restrict__ bc1,
    const float* __restrict__ Wc2,
    const float* __restrict__ bc2,
    float* __restrict__ coors_out)
{
    extern __shared__ float sm[];
    float* We2s = sm;                  // [c][20], c<530, k<16 (padded stride 20)
    float* Fs   = We2s + 10600;        // [c][12], fourier weights rows 256..264
    float* Wc1s = Fs + 6360;           // [16][64]
    float* bc1s = Wc1s + 1024;         // 64
    float* Wc2s = bc1s + 64;           // 64
    float* be2s = Wc2s + 64;           // 16
    float* f_s  = be2s + 16;           // [32][12] per-edge fourier feats
    float* rc_s = f_s + 384;           // [32][4] rel coords
    float* ms   = rc_s + 128;          // [32][16] m_ij
    float* cw_s = ms + 512;            // [32] coor weights
    int*   jj_s = (int*)(cw_s + 32);   // [32] neighbor idx

    int tid = threadIdx.x;
    int w = tid >> 5, lane = tid & 31;
    const unsigned FULL = 0xffffffffu;

    // ---- load weights once per block ----
    for (int idx = tid; idx < 530 * 16; idx += 256)
        We2s[(idx >> 4) * 20 + (idx & 15)] = We2[idx];
    for (int idx = tid; idx < 530 * 9; idx += 256) {
        int t = idx / 530, c = idx - t * 530;
        Fs[c * 12 + t] = We1[(size_t)(256 + t) * 530 + c];
    }
    for (int idx = tid; idx < 16 * 64; idx += 256) Wc1s[idx] = Wc1[idx];
    if (tid < 64) { bc1s[tid] = bc1[tid]; Wc2s[tid] = Wc2[tid]; }
    if (tid < 16) be2s[tid] = be2[tid];
    __syncthreads();

    for (int nn = 0; nn < 4; nn++) {
        int node = blockIdx.x * 4 + nn;
        int b = node >> 12, i = node & (NNODES - 1);
        const float* cb = coors + (size_t)b * NNODES * 3;

        // ---- per-node setup: fourier feats + rel coords (threads 0..31) ----
        if (tid < 32) {
            int e = tid;
            int j = g_knn[(size_t)node * KNN + e];
            jj_s[e] = j;
            float cix = cb[3 * i + 0], ciy = cb[3 * i + 1], ciz = cb[3 * i + 2];
            float dx = cix - cb[3 * j + 0];
            float dy = ciy - cb[3 * j + 1];
            float dz = ciz - cb[3 * j + 2];
            float d = dist2_f(dx, dy, dz);
            rc_s[e * 4 + 0] = dx; rc_s[e * 4 + 1] = dy; rc_s[e * 4 + 2] = dz; rc_s[e * 4 + 3] = 0.f;
            float s0, c0, s1, c1, s2, c2, s3, c3;
            sincosf(d,           &s0, &c0);
            sincosf(d * 0.5f,    &s1, &c1);
            sincosf(d * 0.25f,   &s2, &c2);
            sincosf(d * 0.125f,  &s3, &c3);
            float* fp = &f_s[e * 12];
            fp[0] = s0; fp[1] = s1; fp[2] = s2; fp[3] = s3;
            fp[4] = c0; fp[5] = c1; fp[6] = c2; fp[7] = c3;
            fp[8] = d;  fp[9] = 0.f; fp[10] = 0.f; fp[11] = 0.f;
        }
        __syncthreads();

        // ---- fused edge MLP over this warp's 4 edges ----
        int e0 = w * 4;
        const float* Ap = g_A + (size_t)node * HID;
        const float* Bp0 = g_B + (size_t)(b * NNODES + jj_s[e0 + 0]) * HID;
        const float* Bp1 = g_B + (size_t)(b * NNODES + jj_s[e0 + 1]) * HID;
        const float* Bp2 = g_B + (size_t)(b * NNODES + jj_s[e0 + 2]) * HID;
        const float* Bp3 = g_B + (size_t)(b * NNODES + jj_s[e0 + 3]) * HID;

        float macc[4][16];
#pragma unroll
        for (int q = 0; q < 4; q++)
#pragma unroll
            for (int k = 0; k < 16; k++) macc[q][k] = 0.f;

        for (int it = 0; it < 17; it++) {
            int c = it * 32 + lane;
            if (c < 530) {
                float av  = Ap[c];
                float bv0 = Bp0[c], bv1 = Bp1[c], bv2 = Bp2[c], bv3 = Bp3[c];
                float4 w9a = *reinterpret_cast<const float4*>(&Fs[c * 12]);
                float4 w9b = *reinterpret_cast<const float4*>(&Fs[c * 12 + 4]);
                float  w9c = Fs[c * 12 + 8];
                float4 u0 = *reinterpret_cast<const float4*>(&We2s[c * 20 + 0]);
                float4 u1 = *reinterpret_cast<const float4*>(&We2s[c * 20 + 4]);
                float4 u2 = *reinterpret_cast<const float4*>(&We2s[c * 20 + 8]);
                float4 u3 = *reinterpret_cast<const float4*>(&We2s[c * 20 + 12]);
                float bvs[4] = {bv0, bv1, bv2, bv3};
#pragma unroll
                for (int q = 0; q < 4; q++) {
                    const float* fp = &f_s[(e0 + q) * 12];
                    float4 fa = *reinterpret_cast<const float4*>(fp);
                    float4 fb = *reinterpret_cast<const float4*>(fp + 4);
                    float  fd = fp[8];
                    float h = av + bvs[q];
                    h = fmaf(fa.x, w9a.x, h);
                    h = fmaf(fa.y, w9a.y, h);
                    h = fmaf(fa.z, w9a.z, h);
                    h = fmaf(fa.w, w9a.w, h);
                    h = fmaf(fb.x, w9b.x, h);
                    h = fmaf(fb.y, w9b.y, h);
                    h = fmaf(fb.z, w9b.z, h);
                    h = fmaf(fb.w, w9b.w, h);
                    h = fmaf(fd,   w9c,   h);
                    float sh = silu_f(h);
                    macc[q][0]  = fmaf(sh, u0.x, macc[q][0]);
                    macc[q][1]  = fmaf(sh, u0.y, macc[q][1]);
                    macc[q][2]  = fmaf(sh, u0.z, macc[q][2]);
                    macc[q][3]  = fmaf(sh, u0.w, macc[q][3]);
                    macc[q][4]  = fmaf(sh, u1.x, macc[q][4]);
                    macc[q][5]  = fmaf(sh, u1.y, macc[q][5]);
                    macc[q][6]  = fmaf(sh, u1.z, macc[q][6]);
                    macc[q][7]  = fmaf(sh, u1.w, macc[q][7]);
                    macc[q][8]  = fmaf(sh, u2.x, macc[q][8]);
                    macc[q][9]  = fmaf(sh, u2.y, macc[q][9]);
                    macc[q][10] = fmaf(sh, u2.z, macc[q][10]);
                    macc[q][11] = fmaf(sh, u2.w, macc[q][11]);
                    macc[q][12] = fmaf(sh, u3.x, macc[q][12]);
                    macc[q][13] = fmaf(sh, u3.y, macc[q][13]);
                    macc[q][14] = fmaf(sh, u3.z, macc[q][14]);
                    macc[q][15] = fmaf(sh, u3.w, macc[q][15]);
                }
            }
        }

        // ---- warp reduce -> m_ij ----
#pragma unroll
        for (int q = 0; q < 4; q++)
#pragma unroll
            for (int k = 0; k < 16; k++) {
                float v = macc[q][k];
                v += __shfl_down_sync(FULL, v, 16);
                v += __shfl_down_sync(FULL, v, 8);
                v += __shfl_down_sync(FULL, v, 4);
                v += __shfl_down_sync(FULL, v, 2);
                v += __shfl_down_sync(FULL, v, 1);
                if (lane == 0) ms[(e0 + q) * 16 + k] = silu_f(v + be2s[k]);
            }
        __syncthreads();

        // ---- coors MLP: thread t -> edge t>>3, 8 of 64 hidden units ----
        {
            int e = tid >> 3, li = tid & 7;
            float wpart = 0.f;
#pragma unroll
            for (int q = 0; q < 8; q++) {
                int l = li * 8 + q;
                float u = bc1s[l];
#pragma unroll
                for (int k = 0; k < 16; k++)
                    u = fmaf(ms[e * 16 + k], Wc1s[k * 64 + l], u);
                wpart = fmaf(silu_f(u), Wc2s[l], wpart);
            }
            wpart += __shfl_xor_sync(FULL, wpart, 1);
            wpart += __shfl_xor_sync(FULL, wpart, 2);
            wpart += __shfl_xor_sync(FULL, wpart, 4);
            if (li == 0) cw_s[e] = wpart + bc2[0];
        }
        __syncthreads();

        // ---- m_i -> XC and coors_out ----
        if (tid < 16) {
            float s = 0.f;
#pragma unroll 8
            for (int e2 = 0; e2 < 32; e2++) s += ms[e2 * 16 + tid];
            g_XC[(size_t)node * 144 + 128 + tid] = s;
        }
        if (tid >= 32 && tid < 64) {
            int e2 = tid - 32;
            float wv = cw_s[e2];
            float px = wv * rc_s[e2 * 4 + 0];
            float py = wv * rc_s[e2 * 4 + 1];
            float pz = wv * rc_s[e2 * 4 + 2];
#pragma unroll
            for (int off = 16; off > 0; off >>= 1) {
                px += __shfl_down_sync(FULL, px, off);
                py += __shfl_down_sync(FULL, py, off);
                pz += __shfl_down_sync(FULL, pz, off);
            }
            if (e2 == 0) {
                float* co = coors_out + (size_t)node * 3;
                co[0] = cb[3 * i + 0] + px;
                co[1] = cb[3 * i + 1] + py;
                co[2] = cb[3 * i + 2] + pz;
            }
        }
        __syncthreads();
    }
}

// ---------------------------------------------------------------------------
extern "C" void kernel_launch(void* const* d_in, const int* in_sizes, int n_in,
                              void* d_out, int out_size) {
    const float* feats = (const float*)d_in[0];
    const float* coors = (const float*)d_in[1];
    const float* We1   = (const float*)d_in[2];
    const float* be1   = (const float*)d_in[3];
    const float* We2   = (const float*)d_in[4];
    const float* be2   = (const float*)d_in[5];
    const float* Wc1   = (const float*)d_in[6];
    const float* bc1   = (const float*)d_in[7];
    const float* Wc2   = (const float*)d_in[8];
    const float* bc2   = (const float*)d_in[9];
    const float* Wn1   = (const float*)d_in[10];
    const float* bn1   = (const float*)d_in[11];
    const float* Wn2   = (const float*)d_in[12];
    const float* bn2   = (const float*)d_in[13];
    float* out = (float*)d_out;
    float* node_out  = out;
    float* coors_out = out + NODE_OUT_ELEMS;

    float *pA, *pB, *pXC, *pH1;
    cudaGetSymbolAddress((void**)&pA, g_A);
    cudaGetSymbolAddress((void**)&pB, g_B);
    cudaGetSymbolAddress((void**)&pXC, g_XC);
    cudaGetSymbolAddress((void**)&pH1, g_H1);

    size_t ek_smem = (size_t)EK_SMEM_FLOATS * 4;
    cudaFuncSetAttribute(edge_kernel, cudaFuncAttributeMaxDynamicSharedMemorySize, (int)ek_smem);

    // 1) KNN
    knn_kernel<<<NODES / 8, 256>>>(coors);

    // 2) A = feats @ We1[0:128,:] + be1 ; B = feats @ We1[128:256,:]
    gemm_kernel<<<dim3(9, NODES / 64), 256>>>(feats, DIMF, We1, HID, be1, nullptr,
                                              pA, HID, HID, DIMF, 0);
    gemm_kernel<<<dim3(9, NODES / 64), 256>>>(feats, DIMF, We1 + 128 * HID, HID, nullptr, nullptr,
                                              pB, HID, HID, DIMF, 0);

    // 3) XC[:, 0:128] = feats
    copy_feats_kernel<<<(NODES * DIMF) / 256, 256>>>(feats);

    // 4) edges: m_ij, m_i -> XC[:,128:144], coors_out
    edge_kernel<<<NODES / 4, 256, ek_smem>>>(coors, We1, We2, be2, Wc1, bc1, Wc2, bc2, coors_out);

    // 5) node MLP
    gemm_kernel<<<dim3(4, NODES / 64), 256>>>(pXC, 144, Wn1, 256, bn1, nullptr,
                                              pH1, 256, 256, 144, 1);
    gemm_kernel<<<dim3(2, NODES / 64), 256>>>(pH1, 256, Wn2, DIMF, bn2, feats,
                                              node_out, DIMF, DIMF, 256, 0);
}

// round 3
// speedup vs baseline: 1.3179x; 1.3179x over previous
#include <cuda_runtime.h>
#include <cuda_bf16.h>
#include <math.h>
#include <stdint.h>

#define BB 2
#define NNODES 4096
#define DIMF 128
#define MDIM 16
#define KNN 32
#define HID 530
#define EPAD 544                    // padded hidden (17*32)
#define NODES (BB*NNODES)           // 8192
#define NODE_OUT_ELEMS (NODES*DIMF)

// ---------------- scratch (static device arrays; no allocation) -------------
__device__ float g_A[NODES * EPAD];    // feats@We1[0:128]+be1 (pad cols zero)
__device__ float g_B[NODES * EPAD];    // feats@We1[128:256]   (pad cols zero)
__device__ float g_XC[NODES * 144];    // [feats | m_i]
__device__ float g_H1[NODES * 256];    // node hidden
__device__ int   g_knn[NODES * KNN];

__device__ __forceinline__ float silu_f(float x) {
    float e = __expf(-x);
    return __fdividef(x, 1.0f + e);
}

__device__ __forceinline__ float dist2_f(float dx, float dy, float dz) {
    // match reference (no FMA contraction, left-assoc sum)
    return __fadd_rn(__fadd_rn(__fmul_rn(dx, dx), __fmul_rn(dy, dy)), __fmul_rn(dz, dz));
}

// ---------------------------------------------------------------------------
// KNN: one warp per (b,i). Unsorted top-32 set via warp REDUX threshold.
// ---------------------------------------------------------------------------
__global__ __launch_bounds__(256) void knn_kernel(const float* __restrict__ coors) {
    const unsigned FULL = 0xffffffffu;
    int w    = blockIdx.x * 8 + (threadIdx.x >> 5);
    int lane = threadIdx.x & 31;
    int b = w >> 12;
    int i = w & (NNODES - 1);
    const float* cb = coors + (size_t)b * NNODES * 3;
    float qx = cb[3 * i + 0], qy = cb[3 * i + 1], qz = cb[3 * i + 2];

    float dx = qx - cb[3 * lane + 0];
    float dy = qy - cb[3 * lane + 1];
    float dz = qz - cb[3 * lane + 2];
    unsigned bu = __float_as_uint(dist2_f(dx, dy, dz));
    int bj = lane;
    unsigned curmax = __reduce_max_sync(FULL, bu);

    for (int j0 = 32; j0 < NNODES; j0 += 32) {
        int j = j0 + lane;
        float ex = qx - cb[3 * j + 0];
        float ey = qy - cb[3 * j + 1];
        float ez = qz - cb[3 * j + 2];
        unsigned du = __float_as_uint(dist2_f(ex, ey, ez));
        unsigned mask = __ballot_sync(FULL, du < curmax);
        while (mask) {
            int src = __ffs(mask) - 1;
            mask &= mask - 1;
            unsigned dc = __shfl_sync(FULL, du, src);
            if (dc < curmax) {
                unsigned mm = __ballot_sync(FULL, bu == curmax);
                int ml = __ffs(mm) - 1;
                if (lane == ml) { bu = dc; bj = j0 + src; }
                curmax = __reduce_max_sync(FULL, bu);
            }
        }
    }
    g_knn[(size_t)w * KNN + lane] = bj;
}

// ---------------------------------------------------------------------------
// Tiled fp32 GEMM: C[.. x Npad] = act(X @ W + bias) (+resid)
// Writes all n < Npad; weight/bias reads only n < Nw (else 0) -> zero pads.
// ---------------------------------------------------------------------------
__global__ __launch_bounds__(256) void gemm_kernel(
    const float* __restrict__ X, int ldx,
    const float* __restrict__ W, int ldw,
    const float* __restrict__ bias,
    const float* __restrict__ resid, int ldr,
    float* __restrict__ C, int ldc,
    int Nw, int Npad, int K, int act)
{
    __shared__ float Xs[16][68];
    __shared__ float Ws[16][68];
    int tid = threadIdx.x;
    int tx = tid & 15, ty = tid >> 4;
    int m0 = blockIdx.y * 64, n0 = blockIdx.x * 64;

    int lm  = tid >> 2;
    int lk  = (tid & 3) * 4;
    int wn  = tid & 63;
    int wkb = (tid >> 6) * 4;

    float acc[4][4];
#pragma unroll
    for (int a = 0; a < 4; a++)
#pragma unroll
        for (int c = 0; c < 4; c++) acc[a][c] = 0.f;

    for (int kt = 0; kt < K; kt += 16) {
        float4 xv = *reinterpret_cast<const float4*>(X + (size_t)(m0 + lm) * ldx + kt + lk);
        Xs[lk + 0][lm] = xv.x;
        Xs[lk + 1][lm] = xv.y;
        Xs[lk + 2][lm] = xv.z;
        Xs[lk + 3][lm] = xv.w;
#pragma unroll
        for (int q = 0; q < 4; q++) {
            int k = wkb + q;
            float v = (n0 + wn < Nw) ? W[(size_t)(kt + k) * ldw + n0 + wn] : 0.f;
            Ws[k][wn] = v;
        }
        __syncthreads();
#pragma unroll
        for (int k = 0; k < 16; k++) {
            float4 a4 = *reinterpret_cast<const float4*>(&Xs[k][ty * 4]);
            float4 b4 = *reinterpret_cast<const float4*>(&Ws[k][tx * 4]);
            float av[4] = {a4.x, a4.y, a4.z, a4.w};
            float bv[4] = {b4.x, b4.y, b4.z, b4.w};
#pragma unroll
            for (int mi = 0; mi < 4; mi++)
#pragma unroll
                for (int ni = 0; ni < 4; ni++)
                    acc[mi][ni] = fmaf(av[mi], bv[ni], acc[mi][ni]);
        }
        __syncthreads();
    }

#pragma unroll
    for (int mi = 0; mi < 4; mi++) {
        int m = m0 + ty * 4 + mi;
#pragma unroll
        for (int ni = 0; ni < 4; ni++) {
            int n = n0 + tx * 4 + ni;
            if (n < Npad) {
                float v = acc[mi][ni];
                if (n < Nw) {
                    if (bias) v += bias[n];
                    if (act) v = silu_f(v);
                    if (resid) v += resid[(size_t)m * ldr + n];
                } else {
                    v = 0.f;
                }
                C[(size_t)m * ldc + n] = v;
            }
        }
    }
}

// ---------------------------------------------------------------------------
// copy feats into XC[:, 0:128]
// ---------------------------------------------------------------------------
__global__ __launch_bounds__(256) void copy_feats_kernel(const float* __restrict__ feats) {
    int idx = blockIdx.x * 256 + threadIdx.x;  // over NODES*128
    int n = idx >> 7, c = idx & 127;
    g_XC[(size_t)n * 144 + c] = feats[idx];
}

// ---------------------------------------------------------------------------
// Edge kernel: 512 threads, 4 nodes per block. Warp w (0..15) handles edges
// 2w, 2w+1 of current node; lanes stride 544 channels. Fused second layer in
// 32 register accumulators; reduce-scatter (31 shfl); coors MLP + m_i fused.
// ---------------------------------------------------------------------------
#define EK_SMEM_FLOATS (10880 + 6528 + 1024 + 64 + 64 + 16 + 384 + 128 + 512 + 32 + 32)

__global__ __launch_bounds__(512, 1) void edge_kernel(
    const float* __restrict__ coors,
    const float* __restrict__ We1,
    const float* __restrict__ We2,
    const float* __restrict__ be2,
    const float* __restrict__ Wc1,
    const float* __restrict__ bc1,
    const float* __restrict__ Wc2,
    const float* __restrict__ bc2,
    float* __restrict__ coors_out)
{
    extern __shared__ float sm[];
    float* We2s = sm;                  // [c][20] c<544, k<16 (stride 20)
    float* Fs   = We2s + 10880;        // [c][12] fourier weights rows 256..264
    float* Wc1s = Fs + 6528;           // [16][64]
    float* bc1s = Wc1s + 1024;         // 64
    float* Wc2s = bc1s + 64;           // 64
    float* be2s = Wc2s + 64;           // 16
    float* f_s  = be2s + 16;           // [32][12] per-edge fourier feats
    float* rc_s = f_s + 384;           // [32][4] rel coords
    float* ms   = rc_s + 128;          // [32][16] m_ij
    float* cw_s = ms + 512;            // [32] coor weights
    int*   jj_s = (int*)(cw_s + 32);   // [32] neighbor idx

    int tid = threadIdx.x;
    int w = tid >> 5, lane = tid & 31;
    const unsigned FULL = 0xffffffffu;
    float bc2v = bc2[0];

    // ---- load weights once per block (zero-padded beyond 530) ----
    for (int idx = tid; idx < EPAD * 16; idx += 512) {
        int c = idx >> 4, k = idx & 15;
        We2s[c * 20 + k] = (c < HID) ? We2[c * 16 + k] : 0.f;
    }
    for (int idx = tid; idx < EPAD * 9; idx += 512) {
        int t = idx / EPAD, c = idx - t * EPAD;
        Fs[c * 12 + t] = (c < HID) ? We1[(size_t)(256 + t) * HID + c] : 0.f;
    }
    for (int idx = tid; idx < 16 * 64; idx += 512) Wc1s[idx] = Wc1[idx];
    if (tid < 64) { bc1s[tid] = bc1[tid]; Wc2s[tid] = Wc2[tid]; }
    if (tid >= 64 && tid < 80) be2s[tid - 64] = be2[tid - 64];
    __syncthreads();

    for (int nn = 0; nn < 4; nn++) {
        int node = blockIdx.x * 4 + nn;
        int b = node >> 12, i = node & (NNODES - 1);
        const float* cb = coors + (size_t)b * NNODES * 3;

        // ---- per-node setup (warp 0): fourier feats + rel coords ----
        if (tid < 32) {
            int e = tid;
            int j = g_knn[(size_t)node * KNN + e];
            jj_s[e] = j;
            float dx = cb[3 * i + 0] - cb[3 * j + 0];
            float dy = cb[3 * i + 1] - cb[3 * j + 1];
            float dz = cb[3 * i + 2] - cb[3 * j + 2];
            float d = dist2_f(dx, dy, dz);
            rc_s[e * 4 + 0] = dx; rc_s[e * 4 + 1] = dy; rc_s[e * 4 + 2] = dz; rc_s[e * 4 + 3] = 0.f;
            float s0, c0, s1, c1, s2, c2, s3, c3;
            sincosf(d,          &s0, &c0);
            sincosf(d * 0.5f,   &s1, &c1);
            sincosf(d * 0.25f,  &s2, &c2);
            sincosf(d * 0.125f, &s3, &c3);
            float* fp = &f_s[e * 12];
            fp[0] = s0; fp[1] = s1; fp[2] = s2; fp[3] = s3;
            fp[4] = c0; fp[5] = c1; fp[6] = c2; fp[7] = c3;
            fp[8] = d;  fp[9] = 0.f; fp[10] = 0.f; fp[11] = 0.f;
        }
        __syncthreads();

        // ---- registerize this warp's 2 edges' fourier features ----
        int e0 = w * 2;
        float4 f0a = *reinterpret_cast<const float4*>(&f_s[(e0 + 0) * 12]);
        float4 f0b = *reinterpret_cast<const float4*>(&f_s[(e0 + 0) * 12 + 4]);
        float  f0d = f_s[(e0 + 0) * 12 + 8];
        float4 f1a = *reinterpret_cast<const float4*>(&f_s[(e0 + 1) * 12]);
        float4 f1b = *reinterpret_cast<const float4*>(&f_s[(e0 + 1) * 12 + 4]);
        float  f1d = f_s[(e0 + 1) * 12 + 8];

        const float* Ap  = g_A + (size_t)node * EPAD;
        const float* Bp0 = g_B + (size_t)(b * NNODES + jj_s[e0 + 0]) * EPAD;
        const float* Bp1 = g_B + (size_t)(b * NNODES + jj_s[e0 + 1]) * EPAD;

        float m[32];
#pragma unroll
        for (int q = 0; q < 32; q++) m[q] = 0.f;

        // distance-2 prefetch buffers
        float pav[2], pb0[2], pb1[2];
        pav[0] = Ap[lane];        pav[1] = Ap[32 + lane];
        pb0[0] = Bp0[lane];       pb0[1] = Bp0[32 + lane];
        pb1[0] = Bp1[lane];       pb1[1] = Bp1[32 + lane];

#pragma unroll 2
        for (int it = 0; it < 17; it++) {
            int c = it * 32 + lane;
            int buf = it & 1;
            float av = pav[buf], bv0 = pb0[buf], bv1 = pb1[buf];
            if (it + 2 < 17) {
                int c2 = c + 64;
                pav[buf] = Ap[c2]; pb0[buf] = Bp0[c2]; pb1[buf] = Bp1[c2];
            }
            float4 w9a = *reinterpret_cast<const float4*>(&Fs[c * 12]);
            float4 w9b = *reinterpret_cast<const float4*>(&Fs[c * 12 + 4]);
            float  w9c = Fs[c * 12 + 8];
            float4 u0 = *reinterpret_cast<const float4*>(&We2s[c * 20 + 0]);
            float4 u1 = *reinterpret_cast<const float4*>(&We2s[c * 20 + 4]);
            float4 u2 = *reinterpret_cast<const float4*>(&We2s[c * 20 + 8]);
            float4 u3 = *reinterpret_cast<const float4*>(&We2s[c * 20 + 12]);

            float h0 = av + bv0;
            h0 = fmaf(f0a.x, w9a.x, h0); h0 = fmaf(f0a.y, w9a.y, h0);
            h0 = fmaf(f0a.z, w9a.z, h0); h0 = fmaf(f0a.w, w9a.w, h0);
            h0 = fmaf(f0b.x, w9b.x, h0); h0 = fmaf(f0b.y, w9b.y, h0);
            h0 = fmaf(f0b.z, w9b.z, h0); h0 = fmaf(f0b.w, w9b.w, h0);
            h0 = fmaf(f0d,   w9c,   h0);
            float sh0 = silu_f(h0);

            float h1 = av + bv1;
            h1 = fmaf(f1a.x, w9a.x, h1); h1 = fmaf(f1a.y, w9a.y, h1);
            h1 = fmaf(f1a.z, w9a.z, h1); h1 = fmaf(f1a.w, w9a.w, h1);
            h1 = fmaf(f1b.x, w9b.x, h1); h1 = fmaf(f1b.y, w9b.y, h1);
            h1 = fmaf(f1b.z, w9b.z, h1); h1 = fmaf(f1b.w, w9b.w, h1);
            h1 = fmaf(f1d,   w9c,   h1);
            float sh1 = silu_f(h1);

            m[0]  = fmaf(sh0, u0.x, m[0]);  m[1]  = fmaf(sh0, u0.y, m[1]);
            m[2]  = fmaf(sh0, u0.z, m[2]);  m[3]  = fmaf(sh0, u0.w, m[3]);
            m[4]  = fmaf(sh0, u1.x, m[4]);  m[5]  = fmaf(sh0, u1.y, m[5]);
            m[6]  = fmaf(sh0, u1.z, m[6]);  m[7]  = fmaf(sh0, u1.w, m[7]);
            m[8]  = fmaf(sh0, u2.x, m[8]);  m[9]  = fmaf(sh0, u2.y, m[9]);
            m[10] = fmaf(sh0, u2.z, m[10]); m[11] = fmaf(sh0, u2.w, m[11]);
            m[12] = fmaf(sh0, u3.x, m[12]); m[13] = fmaf(sh0, u3.y, m[13]);
            m[14] = fmaf(sh0, u3.z, m[14]); m[15] = fmaf(sh0, u3.w, m[15]);

            m[16] = fmaf(sh1, u0.x, m[16]); m[17] = fmaf(sh1, u0.y, m[17]);
            m[18] = fmaf(sh1, u0.z, m[18]); m[19] = fmaf(sh1, u0.w, m[19]);
            m[20] = fmaf(sh1, u1.x, m[20]); m[21] = fmaf(sh1, u1.y, m[21]);
            m[22] = fmaf(sh1, u1.z, m[22]); m[23] = fmaf(sh1, u1.w, m[23]);
            m[24] = fmaf(sh1, u2.x, m[24]); m[25] = fmaf(sh1, u2.y, m[25]);
            m[26] = fmaf(sh1, u2.z, m[26]); m[27] = fmaf(sh1, u2.w, m[27]);
            m[28] = fmaf(sh1, u3.x, m[28]); m[29] = fmaf(sh1, u3.y, m[29]);
            m[30] = fmaf(sh1, u3.z, m[30]); m[31] = fmaf(sh1, u3.w, m[31]);
        }

        // ---- reduce-scatter: 31 shfl; final flat index == lane ----
        {
            bool up;
            up = (lane & 16);
#pragma unroll
            for (int v = 0; v < 16; v++) {
                float give = up ? m[v] : m[v + 16];
                float recv = __shfl_xor_sync(FULL, give, 16);
                float keep = up ? m[v + 16] : m[v];
                m[v] = keep + recv;
            }
            up = (lane & 8);
#pragma unroll
            for (int v = 0; v < 8; v++) {
                float give = up ? m[v] : m[v + 8];
                float recv = __shfl_xor_sync(FULL, give, 8);
                float keep = up ? m[v + 8] : m[v];
                m[v] = keep + recv;
            }
            up = (lane & 4);
#pragma unroll
            for (int v = 0; v < 4; v++) {
                float give = up ? m[v] : m[v + 4];
                float recv = __shfl_xor_sync(FULL, give, 4);
                float keep = up ? m[v + 4] : m[v];
                m[v] = keep + recv;
            }
            up = (lane & 2);
#pragma unroll
            for (int v = 0; v < 2; v++) {
                float give = up ? m[v] : m[v + 2];
                float recv = __shfl_xor_sync(FULL, give, 2);
                float keep = up ? m[v + 2] : m[v];
                m[v] = keep + recv;
            }
            up = (lane & 1);
            {
                float give = up ? m[0] : m[1];
                float recv = __shfl_xor_sync(FULL, give, 1);
                float keep = up ? m[1] : m[0];
                m[0] = keep + recv;
            }
            int k = lane & 15, q = lane >> 4;
            ms[(e0 + q) * 16 + k] = silu_f(m[0] + be2s[k]);
        }
        __syncthreads();

        // ---- coors MLP (threads 0-255) and m_i (threads 256-271) ----
        if (tid < 256) {
            int e = tid >> 3, li = tid & 7;
            float wpart = 0.f;
#pragma unroll
            for (int q = 0; q < 8; q++) {
                int l = li * 8 + q;
                float u = bc1s[l];
#pragma unroll
                for (int k = 0; k < 16; k++)
                    u = fmaf(ms[e * 16 + k], Wc1s[k * 64 + l], u);
                wpart = fmaf(silu_f(u), Wc2s[l], wpart);
            }
            wpart += __shfl_xor_sync(FULL, wpart, 1);
            wpart += __shfl_xor_sync(FULL, wpart, 2);
            wpart += __shfl_xor_sync(FULL, wpart, 4);
            if (li == 0) cw_s[e] = wpart + bc2v;
        } else if (tid < 272) {
            int k = tid - 256;
            float s = 0.f;
#pragma unroll 8
            for (int e2 = 0; e2 < 32; e2++) s += ms[e2 * 16 + k];
            g_XC[(size_t)node * 144 + 128 + k] = s;
        }
        __syncthreads();

        // ---- coors_out reduce: warp 0 (program-ordered before next setup) ----
        if (tid < 32) {
            int e2 = tid;
            float wv = cw_s[e2];
            float px = wv * rc_s[e2 * 4 + 0];
            float py = wv * rc_s[e2 * 4 + 1];
            float pz = wv * rc_s[e2 * 4 + 2];
#pragma unroll
            for (int off = 16; off > 0; off >>= 1) {
                px += __shfl_down_sync(FULL, px, off);
                py += __shfl_down_sync(FULL, py, off);
                pz += __shfl_down_sync(FULL, pz, off);
            }
            if (e2 == 0) {
                float* co = coors_out + (size_t)node * 3;
                co[0] = cb[3 * i + 0] + px;
                co[1] = cb[3 * i + 1] + py;
                co[2] = cb[3 * i + 2] + pz;
            }
        }
        // no trailing sync needed: only warp 0 touches rc_s/cw_s next (setup),
        // other warps cross the setup barrier before touching ms/f_s.
    }
}

// ---------------------------------------------------------------------------
extern "C" void kernel_launch(void* const* d_in, const int* in_sizes, int n_in,
                              void* d_out, int out_size) {
    const float* feats = (const float*)d_in[0];
    const float* coors = (const float*)d_in[1];
    const float* We1   = (const float*)d_in[2];
    const float* be1   = (const float*)d_in[3];
    const float* We2   = (const float*)d_in[4];
    const float* be2   = (const float*)d_in[5];
    const float* Wc1   = (const float*)d_in[6];
    const float* bc1   = (const float*)d_in[7];
    const float* Wc2   = (const float*)d_in[8];
    const float* bc2   = (const float*)d_in[9];
    const float* Wn1   = (const float*)d_in[10];
    const float* bn1   = (const float*)d_in[11];
    const float* Wn2   = (const float*)d_in[12];
    const float* bn2   = (const float*)d_in[13];
    float* out = (float*)d_out;
    float* node_out  = out;
    float* coors_out = out + NODE_OUT_ELEMS;

    float *pA, *pB, *pXC, *pH1;
    cudaGetSymbolAddress((void**)&pA, g_A);
    cudaGetSymbolAddress((void**)&pB, g_B);
    cudaGetSymbolAddress((void**)&pXC, g_XC);
    cudaGetSymbolAddress((void**)&pH1, g_H1);

    size_t ek_smem = (size_t)EK_SMEM_FLOATS * 4;
    cudaFuncSetAttribute(edge_kernel, cudaFuncAttributeMaxDynamicSharedMemorySize, (int)ek_smem);

    // 1) KNN
    knn_kernel<<<NODES / 8, 256>>>(coors);

    // 2) A = feats @ We1[0:128,:] + be1 ; B = feats @ We1[128:256,:]  (pad->544)
    gemm_kernel<<<dim3(9, NODES / 64), 256>>>(feats, DIMF, We1, HID, be1, nullptr, 0,
                                              pA, EPAD, HID, EPAD, DIMF, 0);
    gemm_kernel<<<dim3(9, NODES / 64), 256>>>(feats, DIMF, We1 + 128 * HID, HID, nullptr, nullptr, 0,
                                              pB, EPAD, HID, EPAD, DIMF, 0);

    // 3) edges: m_ij -> m_i (XC[:,128:144]), coors_out   (early for ncu window)
    edge_kernel<<<NODES / 4, 512, ek_smem>>>(coors, We1, We2, be2, Wc1, bc1, Wc2, bc2, coors_out);

    // 4) XC[:, 0:128] = feats
    copy_feats_kernel<<<(NODES * DIMF) / 256, 256>>>(feats);

    // 5) node MLP
    gemm_kernel<<<dim3(4, NODES / 64), 256>>>(pXC, 144, Wn1, 256, bn1, nullptr, 0,
                                              pH1, 256, 256, 256, 144, 1);
    gemm_kernel<<<dim3(2, NODES / 64), 256>>>(pH1, 256, Wn2, DIMF, bn2, feats, DIMF,
                                              node_out, DIMF, DIMF, DIMF, 256, 0);
}

// round 4
// speedup vs baseline: 1.3539x; 1.0273x over previous
#include <cuda_runtime.h>
#include <cuda_bf16.h>
#include <math.h>
#include <stdint.h>

#define BB 2
#define NNODES 4096
#define DIMF 128
#define MDIM 16
#define KNN 32
#define HID 530
#define EPAD 544                    // padded hidden (17*32)
#define NODES (BB*NNODES)           // 8192
#define NODE_OUT_ELEMS (NODES*DIMF)

typedef unsigned long long ull;

// ---------------- scratch (static device arrays; no allocation) -------------
__device__ float g_A[NODES * EPAD];    // feats@We1[0:128]+be1 (pad cols zero)
__device__ float g_B[NODES * EPAD];    // feats@We1[128:256]   (pad cols zero)
__device__ float g_XC[NODES * 144];    // [feats | m_i]
__device__ float g_H1[NODES * 256];    // node hidden
__device__ int   g_knn[NODES * KNN];

// ---------------- f32x2 helpers (Blackwell packed fp32) ---------------------
__device__ __forceinline__ ull pack2(float lo, float hi) {
    ull u; asm("mov.b64 %0, {%1, %2};" : "=l"(u) : "f"(lo), "f"(hi)); return u;
}
__device__ __forceinline__ float2 unpack2(ull u) {
    float2 v; asm("mov.b64 {%0, %1}, %2;" : "=f"(v.x), "=f"(v.y) : "l"(u)); return v;
}
__device__ __forceinline__ void ffma2(ull& d, ull a, ull b) {
    asm("fma.rn.f32x2 %0, %1, %2, %0;" : "+l"(d) : "l"(a), "l"(b));
}
__device__ __forceinline__ ull fadd2(ull a, ull b) {
    ull d; asm("add.rn.f32x2 %0, %1, %2;" : "=l"(d) : "l"(a), "l"(b)); return d;
}

__device__ __forceinline__ float silu_f(float x) {
    float e = __expf(-x);
    return __fdividef(x, 1.0f + e);
}

__device__ __forceinline__ float dist2_f(float dx, float dy, float dz) {
    // match reference (no FMA contraction, left-assoc sum)
    return __fadd_rn(__fadd_rn(__fmul_rn(dx, dx), __fmul_rn(dy, dy)), __fmul_rn(dz, dz));
}

// ---------------------------------------------------------------------------
// KNN: one warp per (b,i). Unsorted top-32 set via warp REDUX threshold.
// ---------------------------------------------------------------------------
__global__ __launch_bounds__(256) void knn_kernel(const float* __restrict__ coors) {
    const unsigned FULL = 0xffffffffu;
    int w    = blockIdx.x * 8 + (threadIdx.x >> 5);
    int lane = threadIdx.x & 31;
    int b = w >> 12;
    int i = w & (NNODES - 1);
    const float* cb = coors + (size_t)b * NNODES * 3;
    float qx = cb[3 * i + 0], qy = cb[3 * i + 1], qz = cb[3 * i + 2];

    float dx = qx - cb[3 * lane + 0];
    float dy = qy - cb[3 * lane + 1];
    float dz = qz - cb[3 * lane + 2];
    unsigned bu = __float_as_uint(dist2_f(dx, dy, dz));
    int bj = lane;
    unsigned curmax = __reduce_max_sync(FULL, bu);

    for (int j0 = 32; j0 < NNODES; j0 += 32) {
        int j = j0 + lane;
        float ex = qx - cb[3 * j + 0];
        float ey = qy - cb[3 * j + 1];
        float ez = qz - cb[3 * j + 2];
        unsigned du = __float_as_uint(dist2_f(ex, ey, ez));
        unsigned mask = __ballot_sync(FULL, du < curmax);
        while (mask) {
            int src = __ffs(mask) - 1;
            mask &= mask - 1;
            unsigned dc = __shfl_sync(FULL, du, src);
            if (dc < curmax) {
                unsigned mm = __ballot_sync(FULL, bu == curmax);
                int ml = __ffs(mm) - 1;
                if (lane == ml) { bu = dc; bj = j0 + src; }
                curmax = __reduce_max_sync(FULL, bu);
            }
        }
    }
    g_knn[(size_t)w * KNN + lane] = bj;
}

// ---------------------------------------------------------------------------
// Tiled fp32 GEMM (FFMA2 micro-kernel): C[.. x Npad] = act(X @ W + b) (+resid)
// ---------------------------------------------------------------------------
__global__ __launch_bounds__(256) void gemm_kernel(
    const float* __restrict__ X, int ldx,
    const float* __restrict__ W, int ldw,
    const float* __restrict__ bias,
    const float* __restrict__ resid, int ldr,
    float* __restrict__ C, int ldc,
    int Nw, int Npad, int K, int act)
{
    __shared__ float Xs[16][68];
    __shared__ float Ws[16][68];
    int tid = threadIdx.x;
    int tx = tid & 15, ty = tid >> 4;
    int m0 = blockIdx.y * 64, n0 = blockIdx.x * 64;

    int lm  = tid >> 2;
    int lk  = (tid & 3) * 4;
    int wn  = tid & 63;
    int wkb = (tid >> 6) * 4;

    ull acc2[4][2];
#pragma unroll
    for (int a = 0; a < 4; a++) { acc2[a][0] = 0ull; acc2[a][1] = 0ull; }

    for (int kt = 0; kt < K; kt += 16) {
        float4 xv = *reinterpret_cast<const float4*>(X + (size_t)(m0 + lm) * ldx + kt + lk);
        Xs[lk + 0][lm] = xv.x;
        Xs[lk + 1][lm] = xv.y;
        Xs[lk + 2][lm] = xv.z;
        Xs[lk + 3][lm] = xv.w;
#pragma unroll
        for (int q = 0; q < 4; q++) {
            int k = wkb + q;
            float v = (n0 + wn < Nw) ? W[(size_t)(kt + k) * ldw + n0 + wn] : 0.f;
            Ws[k][wn] = v;
        }
        __syncthreads();
#pragma unroll
        for (int k = 0; k < 16; k++) {
            float4 a4 = *reinterpret_cast<const float4*>(&Xs[k][ty * 4]);
            float4 b4 = *reinterpret_cast<const float4*>(&Ws[k][tx * 4]);
            ull b01 = pack2(b4.x, b4.y);
            ull b23 = pack2(b4.z, b4.w);
            float av[4] = {a4.x, a4.y, a4.z, a4.w};
#pragma unroll
            for (int mi = 0; mi < 4; mi++) {
                ull aa = pack2(av[mi], av[mi]);
                ffma2(acc2[mi][0], aa, b01);
                ffma2(acc2[mi][1], aa, b23);
            }
        }
        __syncthreads();
    }

#pragma unroll
    for (int mi = 0; mi < 4; mi++) {
        int m = m0 + ty * 4 + mi;
        float2 lo = unpack2(acc2[mi][0]);
        float2 hi = unpack2(acc2[mi][1]);
        float accv[4] = {lo.x, lo.y, hi.x, hi.y};
#pragma unroll
        for (int ni = 0; ni < 4; ni++) {
            int n = n0 + tx * 4 + ni;
            if (n < Npad) {
                float v = accv[ni];
                if (n < Nw) {
                    if (bias) v += bias[n];
                    if (act) v = silu_f(v);
                    if (resid) v += resid[(size_t)m * ldr + n];
                } else {
                    v = 0.f;
                }
                C[(size_t)m * ldc + n] = v;
            }
        }
    }
}

// ---------------------------------------------------------------------------
// copy feats into XC[:, 0:128]
// ---------------------------------------------------------------------------
__global__ __launch_bounds__(256) void copy_feats_kernel(const float* __restrict__ feats) {
    int idx = blockIdx.x * 256 + threadIdx.x;  // over NODES*128
    int n = idx >> 7, c = idx & 127;
    g_XC[(size_t)n * 144 + c] = feats[idx];
}

// ---------------------------------------------------------------------------
// Edge kernel: 512 threads, 4 nodes/block, warp handles 2 edges.
// Conflict-free transposed f32x2 weight layouts + FFMA2 inner loop.
// ---------------------------------------------------------------------------
// shared layout in ull units then floats:
#define SM_WE2T   0                         // ull [8][EPAD]
#define SM_FT     (SM_WE2T + 8*EPAD)        // ull [5][EPAD]
#define SM_F2     (SM_FT + 5*EPAD)          // ull [32][6] per-edge fourier pairs
#define SM_ULLS   (SM_F2 + 32*6)
// float region starts at SM_ULLS*2 floats
#define SMF_WC1   0                         // [16][64]
#define SMF_BC1   (SMF_WC1 + 1024)          // 64
#define SMF_WC2   (SMF_BC1 + 64)            // 64
#define SMF_BE2   (SMF_WC2 + 64)            // 16
#define SMF_RC    (SMF_BE2 + 16)            // [32][4]
#define SMF_MS    (SMF_RC + 128)            // [32][16]
#define SMF_CW    (SMF_MS + 512)            // 32
#define SMF_JJ    (SMF_CW + 32)             // 32 ints
#define SMF_TOT   (SMF_JJ + 32)
#define EK_SMEM_BYTES (SM_ULLS*8 + SMF_TOT*4)

__global__ __launch_bounds__(512, 1) void edge_kernel(
    const float* __restrict__ coors,
    const float* __restrict__ We1,
    const float* __restrict__ We2,
    const float* __restrict__ be2,
    const float* __restrict__ Wc1,
    const float* __restrict__ bc1,
    const float* __restrict__ Wc2,
    const float* __restrict__ bc2,
    float* __restrict__ coors_out)
{
    extern __shared__ ull smu[];
    ull* We2T = smu + SM_WE2T;         // We2T[k2*EPAD + c] = (We2[c][2k2], We2[c][2k2+1])
    ull* FT   = smu + SM_FT;           // FT[t2*EPAD + c]   = (W9[2t2][c],  W9[2t2+1][c]) ; t2=4 -> (W9[8][c], 0)
    ull* F2   = smu + SM_F2;           // per-edge fourier pairs
    float* smf  = (float*)(smu + SM_ULLS);
    float* Wc1s = smf + SMF_WC1;
    float* bc1s = smf + SMF_BC1;
    float* Wc2s = smf + SMF_WC2;
    float* be2s = smf + SMF_BE2;
    float* rc_s = smf + SMF_RC;
    float* ms   = smf + SMF_MS;
    float* cw_s = smf + SMF_CW;
    int*   jj_s = (int*)(smf + SMF_JJ);

    int tid = threadIdx.x;
    int w = tid >> 5, lane = tid & 31;
    const unsigned FULL = 0xffffffffu;
    float bc2v = bc2[0];

    // ---- load weights once per block (transposed, packed, zero-padded) ----
    for (int idx = tid; idx < 8 * EPAD; idx += 512) {
        int k2 = idx / EPAD, c = idx - k2 * EPAD;
        ull v = 0ull;
        if (c < HID) v = pack2(We2[c * 16 + 2 * k2], We2[c * 16 + 2 * k2 + 1]);
        We2T[idx] = v;
    }
    for (int idx = tid; idx < 5 * EPAD; idx += 512) {
        int t2 = idx / EPAD, c = idx - t2 * EPAD;
        ull v = 0ull;
        if (c < HID) {
            if (t2 < 4) v = pack2(We1[(size_t)(256 + 2 * t2) * HID + c],
                                  We1[(size_t)(257 + 2 * t2) * HID + c]);
            else        v = pack2(We1[(size_t)264 * HID + c], 0.f);
        }
        FT[idx] = v;
    }
    for (int idx = tid; idx < 16 * 64; idx += 512) Wc1s[idx] = Wc1[idx];
    if (tid < 64) { bc1s[tid] = bc1[tid]; Wc2s[tid] = Wc2[tid]; }
    if (tid >= 64 && tid < 80) be2s[tid - 64] = be2[tid - 64];
    __syncthreads();

    for (int nn = 0; nn < 4; nn++) {
        int node = blockIdx.x * 4 + nn;
        int b = node >> 12, i = node & (NNODES - 1);
        const float* cb = coors + (size_t)b * NNODES * 3;

        // ---- per-node setup (warp 0): fourier pairs + rel coords ----
        if (tid < 32) {
            int e = tid;
            int j = g_knn[(size_t)node * KNN + e];
            jj_s[e] = j;
            float dx = cb[3 * i + 0] - cb[3 * j + 0];
            float dy = cb[3 * i + 1] - cb[3 * j + 1];
            float dz = cb[3 * i + 2] - cb[3 * j + 2];
            float d = dist2_f(dx, dy, dz);
            rc_s[e * 4 + 0] = dx; rc_s[e * 4 + 1] = dy; rc_s[e * 4 + 2] = dz; rc_s[e * 4 + 3] = 0.f;
            float s0, c0, s1, c1, s2, c2, s3, c3;
            sincosf(d,          &s0, &c0);
            sincosf(d * 0.5f,   &s1, &c1);
            sincosf(d * 0.25f,  &s2, &c2);
            sincosf(d * 0.125f, &s3, &c3);
            F2[e * 6 + 0] = pack2(s0, s1);
            F2[e * 6 + 1] = pack2(s2, s3);
            F2[e * 6 + 2] = pack2(c0, c1);
            F2[e * 6 + 3] = pack2(c2, c3);
            F2[e * 6 + 4] = pack2(d, 0.f);
        }
        __syncthreads();

        // ---- registerize this warp's 2 edges' fourier pairs ----
        int e0 = w * 2;
        ull fp0[5], fp1[5];
#pragma unroll
        for (int t = 0; t < 5; t++) { fp0[t] = F2[(e0 + 0) * 6 + t]; fp1[t] = F2[(e0 + 1) * 6 + t]; }

        const float* Ap  = g_A + (size_t)node * EPAD;
        const float* Bp0 = g_B + (size_t)(b * NNODES + jj_s[e0 + 0]) * EPAD;
        const float* Bp1 = g_B + (size_t)(b * NNODES + jj_s[e0 + 1]) * EPAD;

        ull m[16];   // [q][p]: q = edge (0/1), p = output pair 0..7
#pragma unroll
        for (int q = 0; q < 16; q++) m[q] = 0ull;

        // distance-2 prefetch buffers
        float pav[2], pb0[2], pb1[2];
        pav[0] = Ap[lane];        pav[1] = Ap[32 + lane];
        pb0[0] = Bp0[lane];       pb0[1] = Bp0[32 + lane];
        pb1[0] = Bp1[lane];       pb1[1] = Bp1[32 + lane];

#pragma unroll 2
        for (int it = 0; it < 17; it++) {
            int c = it * 32 + lane;
            int buf = it & 1;
            float av = pav[buf], bv0 = pb0[buf], bv1 = pb1[buf];
            if (it + 2 < 17) {
                int c2 = c + 64;
                pav[buf] = Ap[c2]; pb0[buf] = Bp0[c2]; pb1[buf] = Bp1[c2];
            }
            // conflict-free transposed weight loads (lanes consecutive in c)
            ull ft0 = FT[0 * EPAD + c];
            ull ft1 = FT[1 * EPAD + c];
            ull ft2 = FT[2 * EPAD + c];
            ull ft3 = FT[3 * EPAD + c];
            ull ft4 = FT[4 * EPAD + c];

            ull h0p = pack2(av + bv0, 0.f);
            ffma2(h0p, fp0[0], ft0);
            ffma2(h0p, fp0[1], ft1);
            ffma2(h0p, fp0[2], ft2);
            ffma2(h0p, fp0[3], ft3);
            ffma2(h0p, fp0[4], ft4);
            float2 h0v = unpack2(h0p);
            float sh0 = silu_f(h0v.x + h0v.y);

            ull h1p = pack2(av + bv1, 0.f);
            ffma2(h1p, fp1[0], ft0);
            ffma2(h1p, fp1[1], ft1);
            ffma2(h1p, fp1[2], ft2);
            ffma2(h1p, fp1[3], ft3);
            ffma2(h1p, fp1[4], ft4);
            float2 h1v = unpack2(h1p);
            float sh1 = silu_f(h1v.x + h1v.y);

            ull sh0p = pack2(sh0, sh0);
            ull sh1p = pack2(sh1, sh1);

            ull u0 = We2T[0 * EPAD + c];
            ull u1 = We2T[1 * EPAD + c];
            ull u2 = We2T[2 * EPAD + c];
            ull u3 = We2T[3 * EPAD + c];
            ull u4 = We2T[4 * EPAD + c];
            ull u5 = We2T[5 * EPAD + c];
            ull u6 = We2T[6 * EPAD + c];
            ull u7 = We2T[7 * EPAD + c];

            ffma2(m[0], sh0p, u0); ffma2(m[1], sh0p, u1);
            ffma2(m[2], sh0p, u2); ffma2(m[3], sh0p, u3);
            ffma2(m[4], sh0p, u4); ffma2(m[5], sh0p, u5);
            ffma2(m[6], sh0p, u6); ffma2(m[7], sh0p, u7);

            ffma2(m[8],  sh1p, u0); ffma2(m[9],  sh1p, u1);
            ffma2(m[10], sh1p, u2); ffma2(m[11], sh1p, u3);
            ffma2(m[12], sh1p, u4); ffma2(m[13], sh1p, u5);
            ffma2(m[14], sh1p, u6); ffma2(m[15], sh1p, u7);
        }

        // ---- reduce-scatter on 16 f32x2 values; final k = lane&15, q = lane>>4
        {
            bool up;
            up = (lane & 16);
#pragma unroll
            for (int v = 0; v < 8; v++) {
                ull give = up ? m[v] : m[v + 8];
                ull recv = __shfl_xor_sync(FULL, give, 16);
                ull keep = up ? m[v + 8] : m[v];
                m[v] = fadd2(keep, recv);
            }
            up = (lane & 8);
#pragma unroll
            for (int v = 0; v < 4; v++) {
                ull give = up ? m[v] : m[v + 4];
                ull recv = __shfl_xor_sync(FULL, give, 8);
                ull keep = up ? m[v + 4] : m[v];
                m[v] = fadd2(keep, recv);
            }
            up = (lane & 4);
#pragma unroll
            for (int v = 0; v < 2; v++) {
                ull give = up ? m[v] : m[v + 2];
                ull recv = __shfl_xor_sync(FULL, give, 4);
                ull keep = up ? m[v + 2] : m[v];
                m[v] = fadd2(keep, recv);
            }
            up = (lane & 2);
            {
                ull give = up ? m[0] : m[1];
                ull recv = __shfl_xor_sync(FULL, give, 2);
                ull keep = up ? m[1] : m[0];
                m[0] = fadd2(keep, recv);
            }
            float2 v2 = unpack2(m[0]);
            bool upc = (lane & 1);
            float give = upc ? v2.x : v2.y;
            float recv = __shfl_xor_sync(FULL, give, 1);
            float tot = (upc ? v2.y : v2.x) + recv;
            int k = lane & 15, q = lane >> 4;
            ms[(e0 + q) * 16 + k] = silu_f(tot + be2s[k]);
        }
        __syncthreads();

        // ---- coors MLP (threads 0-255) and m_i (threads 256-271) ----
        if (tid < 256) {
            int e = tid >> 3, li = tid & 7;
            float wpart = 0.f;
#pragma unroll
            for (int q = 0; q < 8; q++) {
                int l = li * 8 + q;
                float u = bc1s[l];
#pragma unroll
                for (int k = 0; k < 16; k++)
                    u = fmaf(ms[e * 16 + k], Wc1s[k * 64 + l], u);
                wpart = fmaf(silu_f(u), Wc2s[l], wpart);
            }
            wpart += __shfl_xor_sync(FULL, wpart, 1);
            wpart += __shfl_xor_sync(FULL, wpart, 2);
            wpart += __shfl_xor_sync(FULL, wpart, 4);
            if (li == 0) cw_s[e] = wpart + bc2v;
        } else if (tid < 272) {
            int k = tid - 256;
            float s = 0.f;
#pragma unroll 8
            for (int e2 = 0; e2 < 32; e2++) s += ms[e2 * 16 + k];
            g_XC[(size_t)node * 144 + 128 + k] = s;
        }
        __syncthreads();

        // ---- coors_out reduce: warp 0 ----
        if (tid < 32) {
            int e2 = tid;
            float wv = cw_s[e2];
            float px = wv * rc_s[e2 * 4 + 0];
            float py = wv * rc_s[e2 * 4 + 1];
            float pz = wv * rc_s[e2 * 4 + 2];
#pragma unroll
            for (int off = 16; off > 0; off >>= 1) {
                px += __shfl_down_sync(FULL, px, off);
                py += __shfl_down_sync(FULL, py, off);
                pz += __shfl_down_sync(FULL, pz, off);
            }
            if (e2 == 0) {
                float* co = coors_out + (size_t)node * 3;
                co[0] = cb[3 * i + 0] + px;
                co[1] = cb[3 * i + 1] + py;
                co[2] = cb[3 * i + 2] + pz;
            }
        }
        // warp 0 writes rc_s/F2/jj_s next only after its own reduce (program
        // order); other warps cross the setup __syncthreads before reading.
    }
}

// ---------------------------------------------------------------------------
extern "C" void kernel_launch(void* const* d_in, const int* in_sizes, int n_in,
                              void* d_out, int out_size) {
    const float* feats = (const float*)d_in[0];
    const float* coors = (const float*)d_in[1];
    const float* We1   = (const float*)d_in[2];
    const float* be1   = (const float*)d_in[3];
    const float* We2   = (const float*)d_in[4];
    const float* be2   = (const float*)d_in[5];
    const float* Wc1   = (const float*)d_in[6];
    const float* bc1   = (const float*)d_in[7];
    const float* Wc2   = (const float*)d_in[8];
    const float* bc2   = (const float*)d_in[9];
    const float* Wn1   = (const float*)d_in[10];
    const float* bn1   = (const float*)d_in[11];
    const float* Wn2   = (const float*)d_in[12];
    const float* bn2   = (const float*)d_in[13];
    float* out = (float*)d_out;
    float* node_out  = out;
    float* coors_out = out + NODE_OUT_ELEMS;

    float *pA, *pB, *pXC, *pH1;
    cudaGetSymbolAddress((void**)&pA, g_A);
    cudaGetSymbolAddress((void**)&pB, g_B);
    cudaGetSymbolAddress((void**)&pXC, g_XC);
    cudaGetSymbolAddress((void**)&pH1, g_H1);

    cudaFuncSetAttribute(edge_kernel, cudaFuncAttributeMaxDynamicSharedMemorySize, EK_SMEM_BYTES);

    // 1) KNN
    knn_kernel<<<NODES / 8, 256>>>(coors);

    // 2) A = feats @ We1[0:128,:] + be1 ; B = feats @ We1[128:256,:]  (pad->544)
    gemm_kernel<<<dim3(9, NODES / 64), 256>>>(feats, DIMF, We1, HID, be1, nullptr, 0,
                                              pA, EPAD, HID, EPAD, DIMF, 0);
    gemm_kernel<<<dim3(9, NODES / 64), 256>>>(feats, DIMF, We1 + 128 * HID, HID, nullptr, nullptr, 0,
                                              pB, EPAD, HID, EPAD, DIMF, 0);

    // 3) edges: m_ij -> m_i (XC[:,128:144]), coors_out
    edge_kernel<<<NODES / 4, 512, EK_SMEM_BYTES>>>(coors, We1, We2, be2, Wc1, bc1, Wc2, bc2, coors_out);

    // 4) XC[:, 0:128] = feats
    copy_feats_kernel<<<(NODES * DIMF) / 256, 256>>>(feats);

    // 5) node MLP
    gemm_kernel<<<dim3(4, NODES / 64), 256>>>(pXC, 144, Wn1, 256, bn1, nullptr, 0,
                                              pH1, 256, 256, 256, 144, 1);
    gemm_kernel<<<dim3(2, NODES / 64), 256>>>(pH1, 256, Wn2, DIMF, bn2, feats, DIMF,
                                              node_out, DIMF, DIMF, DIMF, 256, 0);
}